// round 1
// baseline (speedup 1.0000x reference)
#include <cuda_runtime.h>

#define NQ      10
#define DIM     1024
#define NLAYERS 6
#define BATCH   16384

// 60 gate matrices: [layer][qubit][u00.re,u00.im,u01.re,u01.im,u10.re,u10.im,u11.re,u11.im]
__device__ __align__(16) float g_gates[NLAYERS][NQ][8];

// ---------------------------------------------------------------------------
// Pre-kernel: build the 2x2 Rot matrices once (saves MUFU in the hot kernel).
// ---------------------------------------------------------------------------
__global__ void precompute_kernel(const float* __restrict__ qlayers) {
    int i = threadIdx.x;
    if (i >= NLAYERS * NQ) return;
    int l = i / NQ, w = i % NQ;
    float phi   = qlayers[(l * NQ + w) * 3 + 0];
    float theta = qlayers[(l * NQ + w) * 3 + 1];
    float omega = qlayers[(l * NQ + w) * 3 + 2];
    float s, c;  sincosf(0.5f * theta, &s, &c);
    float sp, cp; sincosf(0.5f * (phi + omega), &sp, &cp);
    float sm, cm; sincosf(0.5f * (phi - omega), &sm, &cm);
    float* g = g_gates[l][w];
    // u00 = e^{-i(phi+omega)/2} * c
    g[0] =  cp * c;  g[1] = -sp * c;
    // u01 = -e^{ i(phi-omega)/2} * s
    g[2] = -cm * s;  g[3] = -sm * s;
    // u10 =  e^{-i(phi-omega)/2} * s
    g[4] =  cm * s;  g[5] = -sm * s;
    // u11 =  e^{ i(phi+omega)/2} * c
    g[6] =  cp * c;  g[7] =  sp * c;
}

// ---------------------------------------------------------------------------
// Gate chain: qubit Q acts on amplitude bit B = 9-Q.
// Bits 0..4 = per-thread local index j, bits 5..9 = lane bits.
// ---------------------------------------------------------------------------
template<int Q>
__device__ __forceinline__ void gate_chain(float re[32], float im[32], int lane,
                                           const float4* __restrict__ gp) {
    if constexpr (Q < NQ) {
        const float4 ua = __ldg(gp + 2 * Q);      // u00, u01
        const float4 ub = __ldg(gp + 2 * Q + 1);  // u10, u11
        constexpr int B = 9 - Q;
        if constexpr (B >= 5) {
            // lane-bit gate: pair exchange via shfl_xor
            constexpr unsigned msk = 1u << (B - 5);
            const bool hi = (lane >> (B - 5)) & 1;
            const float mr = hi ? ub.z : ua.x;   // coeff for my amplitude
            const float mi = hi ? ub.w : ua.y;
            const float pr = hi ? ub.x : ua.z;   // coeff for partner amplitude
            const float pi = hi ? ub.y : ua.w;
            #pragma unroll
            for (int j = 0; j < 32; ++j) {
                float qr = __shfl_xor_sync(0xffffffffu, re[j], msk);
                float qi = __shfl_xor_sync(0xffffffffu, im[j], msk);
                float r0 = re[j], i0 = im[j];
                re[j] = mr * r0 - mi * i0 + pr * qr - pi * qi;
                im[j] = mr * i0 + mi * r0 + pr * qi + pi * qr;
            }
        } else {
            // local-bit gate: register-only 2x2 complex matvec on 16 pairs
            #pragma unroll
            for (int j = 0; j < 32; ++j) {
                if (!(j & (1 << B))) {
                    const int j2 = j | (1 << B);
                    float ar = re[j],  ai = im[j];
                    float br = re[j2], bi = im[j2];
                    re[j]  = ua.x * ar - ua.y * ai + ua.z * br - ua.w * bi;
                    im[j]  = ua.x * ai + ua.y * ar + ua.z * bi + ua.w * br;
                    re[j2] = ub.x * ar - ub.y * ai + ub.z * br - ub.w * bi;
                    im[j2] = ub.x * ai + ub.y * ar + ub.z * bi + ub.w * br;
                }
            }
        }
        gate_chain<Q + 1>(re, im, lane, gp);
    }
}

// ---------------------------------------------------------------------------
// CNOT: control bit BC, target bit BT (amplitude-bit indices).
// ---------------------------------------------------------------------------
template<int BC, int BT>
__device__ __forceinline__ void cnot_gate(float re[32], float im[32], int lane) {
    if constexpr (BC < 5 && BT < 5) {
        // both local: pure register swap
        #pragma unroll
        for (int j = 0; j < 32; ++j) {
            if (((j >> BC) & 1) && !((j >> BT) & 1)) {
                const int j2 = j | (1 << BT);
                float t;
                t = re[j]; re[j] = re[j2]; re[j2] = t;
                t = im[j]; im[j] = im[j2]; im[j2] = t;
            }
        }
    } else if constexpr (BC >= 5 && BT < 5) {
        // lane-controlled local swap (predicated)
        const bool ctl = (lane >> (BC - 5)) & 1;
        #pragma unroll
        for (int j = 0; j < 32; ++j) {
            if (!((j >> BT) & 1)) {
                const int j2 = j | (1 << BT);
                float r0 = re[j], r1 = re[j2];
                float i0 = im[j], i1 = im[j2];
                re[j]  = ctl ? r1 : r0;  re[j2] = ctl ? r0 : r1;
                im[j]  = ctl ? i1 : i0;  im[j2] = ctl ? i0 : i1;
            }
        }
    } else if constexpr (BC < 5 && BT >= 5) {
        // local-controlled cross-lane exchange (uniform condition, full warp)
        constexpr unsigned msk = 1u << (BT - 5);
        #pragma unroll
        for (int j = 0; j < 32; ++j) {
            if ((j >> BC) & 1) {
                re[j] = __shfl_xor_sync(0xffffffffu, re[j], msk);
                im[j] = __shfl_xor_sync(0xffffffffu, im[j], msk);
            }
        }
    } else {
        // lane-controlled cross-lane exchange (predicated select)
        constexpr unsigned msk = 1u << (BT - 5);
        const bool ctl = (lane >> (BC - 5)) & 1;
        #pragma unroll
        for (int j = 0; j < 32; ++j) {
            float qr = __shfl_xor_sync(0xffffffffu, re[j], msk);
            float qi = __shfl_xor_sync(0xffffffffu, im[j], msk);
            re[j] = ctl ? qr : re[j];
            im[j] = ctl ? qi : im[j];
        }
    }
}

template<int R, int W>
__device__ __forceinline__ void cnot_chain(float re[32], float im[32], int lane) {
    if constexpr (W < NQ) {
        constexpr int T = (W + R) % NQ;
        cnot_gate<9 - W, 9 - T>(re, im, lane);
        cnot_chain<R, W + 1>(re, im, lane);
    }
}

// ---------------------------------------------------------------------------
// Main kernel: one warp per batch sample, state in registers.
// ---------------------------------------------------------------------------
__global__ void __launch_bounds__(256) qcnn_kernel(
    const float* __restrict__ x,
    const float* __restrict__ fc_w,
    const float* __restrict__ fc_b,
    float* __restrict__ out)
{
    const int warp = (blockIdx.x * blockDim.x + threadIdx.x) >> 5;
    const int lane = threadIdx.x & 31;
    if (warp >= BATCH) return;

    // --- initial product state ---------------------------------------------
    const float* xb = x + warp * NQ;
    float cq[NQ], sq[NQ];
    #pragma unroll
    for (int q = 0; q < NQ; ++q) {
        float h = 0.5f * __ldg(xb + q);
        sincosf(h, &sq[q], &cq[q]);
    }
    // qubit q in 0..4 lives on lane bit (4-q)
    float A = 1.f;
    #pragma unroll
    for (int q = 0; q < 5; ++q)
        A *= ((lane >> (4 - q)) & 1) ? sq[q] : cq[q];

    float re[32], im[32];
    re[0] = A;
    // qubit q in 5..9 lives on local bit (9-q): doubling build
    #pragma unroll
    for (int t = 0; t < 5; ++t) {
        const int q = 9 - t;
        const int sz = 1 << t;
        #pragma unroll
        for (int k = sz - 1; k >= 0; --k) {
            float m = re[k];
            re[k + sz] = m * sq[q];
            re[k]      = m * cq[q];
        }
    }
    // phase (-i)^popcount(n): 4 classes by popcount mod 4
    const int pl = __popc(lane);
    float rmul[4], imul[4];
    #pragma unroll
    for (int c = 0; c < 4; ++c) {
        int k = (pl + c) & 3;
        rmul[c] = (k == 0) ? 1.f : ((k == 2) ? -1.f : 0.f);
        imul[c] = (k == 3) ? 1.f : ((k == 1) ? -1.f : 0.f);
    }
    #pragma unroll
    for (int j = 0; j < 32; ++j) {
        const int c = __popc(j) & 3;   // compile-time
        float m = re[j];
        re[j] = m * rmul[c];
        im[j] = m * imul[c];
    }

    // --- circuit ------------------------------------------------------------
    #pragma unroll 1
    for (int l = 0; l < NLAYERS; ++l) {
        const float4* gp = reinterpret_cast<const float4*>(g_gates[l]);
        gate_chain<0>(re, im, lane, gp);
        switch (l) {   // r = l % (NQ-1) + 1 = l+1 for l in 0..5
            case 0: cnot_chain<1, 0>(re, im, lane); break;
            case 1: cnot_chain<2, 0>(re, im, lane); break;
            case 2: cnot_chain<3, 0>(re, im, lane); break;
            case 3: cnot_chain<4, 0>(re, im, lane); break;
            case 4: cnot_chain<5, 0>(re, im, lane); break;
            default: cnot_chain<6, 0>(re, im, lane); break;
        }
    }

    // --- epilogue: sum_i w_i * |psi_i|^2,  w_i = sum_q fc_w[q]*(1-2*bit_q(i))
    float f[NQ];
    #pragma unroll
    for (int q = 0; q < NQ; ++q) f[q] = __ldg(fc_w + q);

    float wl = 0.f;
    #pragma unroll
    for (int q = 0; q < 5; ++q)
        wl += ((lane >> (4 - q)) & 1) ? -f[q] : f[q];

    float acc = 0.f;
    #pragma unroll
    for (int j = 0; j < 32; ++j) {
        float w = wl;                          // compile-time signs below
        w += (j & 16) ? -f[5] : f[5];
        w += (j &  8) ? -f[6] : f[6];
        w += (j &  4) ? -f[7] : f[7];
        w += (j &  2) ? -f[8] : f[8];
        w += (j &  1) ? -f[9] : f[9];
        float p = re[j] * re[j] + im[j] * im[j];
        acc += w * p;
    }
    #pragma unroll
    for (int off = 16; off; off >>= 1)
        acc += __shfl_xor_sync(0xffffffffu, acc, off);

    if (lane == 0) out[warp] = acc + __ldg(fc_b);
}

// ---------------------------------------------------------------------------
extern "C" void kernel_launch(void* const* d_in, const int* in_sizes, int n_in,
                              void* d_out, int out_size) {
    const float* x    = (const float*)d_in[0];   // (16384, 10)
    const float* ql   = (const float*)d_in[1];   // (6, 10, 3)
    const float* fcw  = (const float*)d_in[2];   // (1, 10)
    const float* fcb  = (const float*)d_in[3];   // (1,)
    float* out = (float*)d_out;                  // (16384, 1)

    precompute_kernel<<<1, 64>>>(ql);
    qcnn_kernel<<<BATCH / 8, 256>>>(x, fcw, fcb, out);
}

// round 2
// speedup vs baseline: 1.1601x; 1.1601x over previous
#include <cuda_runtime.h>

#define NQ      10
#define DIM     1024
#define NLAYERS 6
#define BATCH   16384

// 60 gate matrices: [layer][qubit][u00.re,u00.im,u01.re,u01.im,u10.re,u10.im,u11.re,u11.im]
__device__ __align__(16) float g_gates[NLAYERS][NQ][8];

// ---------------------------------------------------------------------------
// Packed f32x2 helpers (SASS FFMA2/FMUL2/FADD2 — ptxas never emits these from C++)
// ---------------------------------------------------------------------------
__device__ __forceinline__ float2 ffma2_(float2 a, float2 b, float2 c) {
    float2 d;
    asm("{\n\t.reg .b64 A,B,C,D;\n\t"
        "mov.b64 A,{%2,%3};\n\t mov.b64 B,{%4,%5};\n\t mov.b64 C,{%6,%7};\n\t"
        "fma.rn.f32x2 D,A,B,C;\n\t"
        "mov.b64 {%0,%1},D;\n\t}"
        : "=f"(d.x), "=f"(d.y)
        : "f"(a.x), "f"(a.y), "f"(b.x), "f"(b.y), "f"(c.x), "f"(c.y));
    return d;
}
__device__ __forceinline__ float2 fmul2_(float2 a, float2 b) {
    float2 d;
    asm("{\n\t.reg .b64 A,B,D;\n\t"
        "mov.b64 A,{%2,%3};\n\t mov.b64 B,{%4,%5};\n\t"
        "mul.rn.f32x2 D,A,B;\n\t"
        "mov.b64 {%0,%1},D;\n\t}"
        : "=f"(d.x), "=f"(d.y)
        : "f"(a.x), "f"(a.y), "f"(b.x), "f"(b.y));
    return d;
}
__device__ __forceinline__ float2 fsub2_(float2 a, float2 b) {
    float2 d;
    asm("{\n\t.reg .b64 A,B,D;\n\t"
        "mov.b64 A,{%2,%3};\n\t mov.b64 B,{%4,%5};\n\t"
        "sub.rn.f32x2 D,A,B;\n\t"
        "mov.b64 {%0,%1},D;\n\t}"
        : "=f"(d.x), "=f"(d.y)
        : "f"(a.x), "f"(a.y), "f"(b.x), "f"(b.y));
    return d;
}
__device__ __forceinline__ float2 bc2(float v) { return make_float2(v, v); }

// ---------------------------------------------------------------------------
// Pre-kernel: build the 2x2 Rot matrices once.
// ---------------------------------------------------------------------------
__global__ void precompute_kernel(const float* __restrict__ qlayers) {
    int i = threadIdx.x;
    if (i >= NLAYERS * NQ) return;
    int l = i / NQ, w = i % NQ;
    float phi   = qlayers[(l * NQ + w) * 3 + 0];
    float theta = qlayers[(l * NQ + w) * 3 + 1];
    float omega = qlayers[(l * NQ + w) * 3 + 2];
    float s, c;  sincosf(0.5f * theta, &s, &c);
    float sp, cp; sincosf(0.5f * (phi + omega), &sp, &cp);
    float sm, cm; sincosf(0.5f * (phi - omega), &sm, &cm);
    float* g = g_gates[l][w];
    g[0] =  cp * c;  g[1] = -sp * c;   // u00
    g[2] = -cm * s;  g[3] = -sm * s;   // u01
    g[4] =  cm * s;  g[5] = -sm * s;   // u10
    g[6] =  cp * c;  g[7] =  sp * c;   // u11
}

// ---------------------------------------------------------------------------
// State layout: amplitude index n (10 bits).
//   bits 9..5 -> lane bits (lane bit B-5), bits 4..1 -> pack index k (bit B-1),
//   bit 0     -> f32x2 component.
// Qubit q acts on bit B = 9-q.
// State: sr[16], si[16] (float2 = 2 amplitudes each).
// ---------------------------------------------------------------------------
template<int Q>
__device__ __forceinline__ void gate_chain(float2 sr[16], float2 si[16], int lane,
                                           const float4* __restrict__ gp) {
    if constexpr (Q < NQ) {
        const float4 ua = __ldg(gp + 2 * Q);      // u00, u01
        const float4 ub = __ldg(gp + 2 * Q + 1);  // u10, u11
        constexpr int B = 9 - Q;
        if constexpr (B >= 5) {
            // lane-bit gate: pair exchange via shfl_xor, packed math
            constexpr unsigned msk = 1u << (B - 5);
            const bool hi = (lane >> (B - 5)) & 1;
            const float2 mr2 = bc2(hi ? ub.z : ua.x);
            const float2 mi2 = bc2(hi ? ub.w : ua.y);
            const float2 pr2 = bc2(hi ? ub.x : ua.z);
            const float2 pi2 = bc2(hi ? ub.y : ua.w);
            #pragma unroll
            for (int k = 0; k < 16; ++k) {
                float2 qr, qi;
                qr.x = __shfl_xor_sync(0xffffffffu, sr[k].x, msk);
                qr.y = __shfl_xor_sync(0xffffffffu, sr[k].y, msk);
                qi.x = __shfl_xor_sync(0xffffffffu, si[k].x, msk);
                qi.y = __shfl_xor_sync(0xffffffffu, si[k].y, msk);
                float2 r0 = sr[k], i0 = si[k];
                // re' = (mr*r0 + pr*qr) - (mi*i0 + pi*qi)
                sr[k] = fsub2_(ffma2_(pr2, qr, fmul2_(mr2, r0)),
                               ffma2_(pi2, qi, fmul2_(mi2, i0)));
                // im' = mr*i0 + mi*r0 + pr*qi + pi*qr
                si[k] = ffma2_(mr2, i0, ffma2_(mi2, r0,
                               ffma2_(pr2, qi, fmul2_(pi2, qr))));
            }
        } else if constexpr (B >= 1) {
            // pack-local gate on pack bit pb = B-1
            constexpr int pb = B - 1;
            const float2 uax2 = bc2(ua.x), uay2 = bc2(ua.y);
            const float2 uaz2 = bc2(ua.z), uaw2 = bc2(ua.w);
            const float2 ubx2 = bc2(ub.x), uby2 = bc2(ub.y);
            const float2 ubz2 = bc2(ub.z), ubw2 = bc2(ub.w);
            #pragma unroll
            for (int k = 0; k < 16; ++k) {
                if (!(k & (1 << pb))) {
                    const int k2 = k | (1 << pb);
                    float2 ar = sr[k],  ai = si[k];
                    float2 br = sr[k2], bi = si[k2];
                    sr[k]  = fsub2_(ffma2_(uaz2, br, fmul2_(uax2, ar)),
                                    ffma2_(uaw2, bi, fmul2_(uay2, ai)));
                    si[k]  = ffma2_(uax2, ai, ffma2_(uay2, ar,
                                    ffma2_(uaz2, bi, fmul2_(uaw2, br))));
                    sr[k2] = fsub2_(ffma2_(ubz2, br, fmul2_(ubx2, ar)),
                                    ffma2_(ubw2, bi, fmul2_(uby2, ai)));
                    si[k2] = ffma2_(ubx2, ai, ffma2_(uby2, ar,
                                    ffma2_(ubz2, bi, fmul2_(ubw2, br))));
                }
            }
        } else {
            // B == 0: intra-pack gate.  a = comp 0, b = comp 1
            // a' = u00*a + u01*b ; b' = u10*a + u11*b
            const float2 C1r = make_float2(ua.x, ub.z);
            const float2 C1i = make_float2(ua.y, ub.w);
            const float2 C2r = make_float2(ua.z, ub.x);
            const float2 C2i = make_float2(ua.w, ub.y);
            #pragma unroll
            for (int k = 0; k < 16; ++k) {
                float2 vr = sr[k], vi = si[k];
                float2 wr = make_float2(vr.y, vr.x);
                float2 wi = make_float2(vi.y, vi.x);
                sr[k] = fsub2_(ffma2_(C2r, wr, fmul2_(C1r, vr)),
                               ffma2_(C2i, wi, fmul2_(C1i, vi)));
                si[k] = ffma2_(C1r, vi, ffma2_(C1i, vr,
                               ffma2_(C2r, wi, fmul2_(C2i, wr))));
            }
        }
        gate_chain<Q + 1>(sr, si, lane, gp);
    }
}

// ---------------------------------------------------------------------------
// CNOT: control bit BC, target bit BT (amplitude-bit indices).
// ---------------------------------------------------------------------------
template<int BC, int BT>
__device__ __forceinline__ void cnot_gate(float2 sr[16], float2 si[16], int lane) {
    if constexpr (BC >= 5 && BT >= 5) {
        // lane ctrl, lane target: predicated shfl exchange
        constexpr unsigned msk = 1u << (BT - 5);
        const bool ctl = (lane >> (BC - 5)) & 1;
        #pragma unroll
        for (int k = 0; k < 16; ++k) {
            float2 qr, qi;
            qr.x = __shfl_xor_sync(0xffffffffu, sr[k].x, msk);
            qr.y = __shfl_xor_sync(0xffffffffu, sr[k].y, msk);
            qi.x = __shfl_xor_sync(0xffffffffu, si[k].x, msk);
            qi.y = __shfl_xor_sync(0xffffffffu, si[k].y, msk);
            sr[k].x = ctl ? qr.x : sr[k].x;  sr[k].y = ctl ? qr.y : sr[k].y;
            si[k].x = ctl ? qi.x : si[k].x;  si[k].y = ctl ? qi.y : si[k].y;
        }
    } else if constexpr (BC >= 5 && BT >= 1) {
        // lane ctrl, pack-local target
        constexpr int pb = BT - 1;
        const bool ctl = (lane >> (BC - 5)) & 1;
        #pragma unroll
        for (int k = 0; k < 16; ++k) {
            if (!((k >> pb) & 1)) {
                const int k2 = k | (1 << pb);
                float2 r0 = sr[k], r1 = sr[k2];
                float2 i0 = si[k], i1 = si[k2];
                sr[k].x  = ctl ? r1.x : r0.x;  sr[k].y  = ctl ? r1.y : r0.y;
                sr[k2].x = ctl ? r0.x : r1.x;  sr[k2].y = ctl ? r0.y : r1.y;
                si[k].x  = ctl ? i1.x : i0.x;  si[k].y  = ctl ? i1.y : i0.y;
                si[k2].x = ctl ? i0.x : i1.x;  si[k2].y = ctl ? i0.y : i1.y;
            }
        }
    } else if constexpr (BC >= 5 && BT == 0) {
        // lane ctrl, component target: conditional component swap
        const bool ctl = (lane >> (BC - 5)) & 1;
        #pragma unroll
        for (int k = 0; k < 16; ++k) {
            float2 vr = sr[k], vi = si[k];
            sr[k].x = ctl ? vr.y : vr.x;  sr[k].y = ctl ? vr.x : vr.y;
            si[k].x = ctl ? vi.y : vi.x;  si[k].y = ctl ? vi.x : vi.y;
        }
    } else if constexpr (BC >= 1 && BT >= 5) {
        // pack-local ctrl, lane target: shfl only packs with ctrl bit set (half)
        constexpr unsigned msk = 1u << (BT - 5);
        constexpr int pb = BC - 1;
        #pragma unroll
        for (int k = 0; k < 16; ++k) {
            if ((k >> pb) & 1) {
                sr[k].x = __shfl_xor_sync(0xffffffffu, sr[k].x, msk);
                sr[k].y = __shfl_xor_sync(0xffffffffu, sr[k].y, msk);
                si[k].x = __shfl_xor_sync(0xffffffffu, si[k].x, msk);
                si[k].y = __shfl_xor_sync(0xffffffffu, si[k].y, msk);
            }
        }
    } else if constexpr (BC >= 1 && BT >= 1) {
        // both pack-local: pure register permutation (free)
        constexpr int pbc = BC - 1, pbt = BT - 1;
        #pragma unroll
        for (int k = 0; k < 16; ++k) {
            if (((k >> pbc) & 1) && !((k >> pbt) & 1)) {
                const int k2 = k | (1 << pbt);
                float2 t;
                t = sr[k]; sr[k] = sr[k2]; sr[k2] = t;
                t = si[k]; si[k] = si[k2]; si[k2] = t;
            }
        }
    } else if constexpr (BC >= 1 && BT == 0) {
        // pack-local ctrl, component target: comp swap on ctrl packs (free)
        constexpr int pb = BC - 1;
        #pragma unroll
        for (int k = 0; k < 16; ++k) {
            if ((k >> pb) & 1) {
                float t;
                t = sr[k].x; sr[k].x = sr[k].y; sr[k].y = t;
                t = si[k].x; si[k].x = si[k].y; si[k].y = t;
            }
        }
    } else if constexpr (BC == 0 && BT >= 5) {
        // component ctrl, lane target: shfl only .y components (half shfl count)
        constexpr unsigned msk = 1u << (BT - 5);
        #pragma unroll
        for (int k = 0; k < 16; ++k) {
            sr[k].y = __shfl_xor_sync(0xffffffffu, sr[k].y, msk);
            si[k].y = __shfl_xor_sync(0xffffffffu, si[k].y, msk);
        }
    } else {
        // component ctrl, pack-local target: swap .y fields (free)
        constexpr int pb = BT - 1;
        #pragma unroll
        for (int k = 0; k < 16; ++k) {
            if (!((k >> pb) & 1)) {
                const int k2 = k | (1 << pb);
                float t;
                t = sr[k].y; sr[k].y = sr[k2].y; sr[k2].y = t;
                t = si[k].y; si[k].y = si[k2].y; si[k2].y = t;
            }
        }
    }
}

template<int R, int W>
__device__ __forceinline__ void cnot_chain(float2 sr[16], float2 si[16], int lane) {
    if constexpr (W < NQ) {
        constexpr int T = (W + R) % NQ;
        cnot_gate<9 - W, 9 - T>(sr, si, lane);
        cnot_chain<R, W + 1>(sr, si, lane);
    }
}

// ---------------------------------------------------------------------------
// Main kernel: one warp per batch sample, state in registers (f32x2 packed).
// ---------------------------------------------------------------------------
__global__ void __launch_bounds__(256, 2) qcnn_kernel(
    const float* __restrict__ x,
    const float* __restrict__ fc_w,
    const float* __restrict__ fc_b,
    float* __restrict__ out)
{
    const int warp = (blockIdx.x * blockDim.x + threadIdx.x) >> 5;
    const int lane = threadIdx.x & 31;
    if (warp >= BATCH) return;

    // --- initial product state ---------------------------------------------
    const float* xb = x + warp * NQ;
    float cq[NQ], sq[NQ];
    #pragma unroll
    for (int q = 0; q < NQ; ++q) {
        float h = 0.5f * __ldg(xb + q);
        sincosf(h, &sq[q], &cq[q]);
    }
    // qubits 0..4 on lane bits (qubit q -> lane bit 4-q)
    float A = 1.f;
    #pragma unroll
    for (int q = 0; q < 5; ++q)
        A *= ((lane >> (4 - q)) & 1) ? sq[q] : cq[q];

    // magnitudes over pack index k (k bit t -> qubit 8-t), comp -> qubit 9
    float m[16];
    m[0] = A;
    #pragma unroll
    for (int t = 0; t < 4; ++t) {
        const int q = 8 - t;
        const int sz = 1 << t;
        #pragma unroll
        for (int k = sz - 1; k >= 0; --k) {
            float v = m[k];
            m[k + sz] = v * sq[q];
            m[k]      = v * cq[q];
        }
    }
    // phase (-i)^popcount(n)
    const int pl = __popc(lane);
    float rmul[4], imul[4];
    #pragma unroll
    for (int c = 0; c < 4; ++c) {
        int kk = (pl + c) & 3;
        rmul[c] = (kk == 0) ? 1.f : ((kk == 2) ? -1.f : 0.f);
        imul[c] = (kk == 3) ? 1.f : ((kk == 1) ? -1.f : 0.f);
    }
    float2 sr[16], si[16];
    #pragma unroll
    for (int k = 0; k < 16; ++k) {
        const int c0 = __popc(k) & 3;           // compile-time
        const int c1 = (__popc(k) + 1) & 3;
        float mag0 = m[k] * cq[9];
        float mag1 = m[k] * sq[9];
        sr[k] = make_float2(mag0 * rmul[c0], mag1 * rmul[c1]);
        si[k] = make_float2(mag0 * imul[c0], mag1 * imul[c1]);
    }

    // --- circuit ------------------------------------------------------------
    #pragma unroll 1
    for (int l = 0; l < NLAYERS; ++l) {
        const float4* gp = reinterpret_cast<const float4*>(g_gates[l]);
        gate_chain<0>(sr, si, lane, gp);
        switch (l) {   // r = l+1 for l in 0..5
            case 0: cnot_chain<1, 0>(sr, si, lane); break;
            case 1: cnot_chain<2, 0>(sr, si, lane); break;
            case 2: cnot_chain<3, 0>(sr, si, lane); break;
            case 3: cnot_chain<4, 0>(sr, si, lane); break;
            case 4: cnot_chain<5, 0>(sr, si, lane); break;
            default: cnot_chain<6, 0>(sr, si, lane); break;
        }
    }

    // --- epilogue: sum_i w_i * |psi_i|^2 ------------------------------------
    float f[NQ];
    #pragma unroll
    for (int q = 0; q < NQ; ++q) f[q] = __ldg(fc_w + q);

    float wl = 0.f;
    #pragma unroll
    for (int q = 0; q < 5; ++q)
        wl += ((lane >> (4 - q)) & 1) ? -f[q] : f[q];

    float2 acc2 = make_float2(0.f, 0.f);
    #pragma unroll
    for (int k = 0; k < 16; ++k) {
        float base = wl;                        // k bit t -> qubit 8-t -> f[8-t]
        base += (k & 1) ? -f[8] : f[8];
        base += (k & 2) ? -f[7] : f[7];
        base += (k & 4) ? -f[6] : f[6];
        base += (k & 8) ? -f[5] : f[5];
        float2 w2 = make_float2(base + f[9], base - f[9]);   // comp = qubit 9
        float2 p2 = ffma2_(si[k], si[k], fmul2_(sr[k], sr[k]));
        acc2 = ffma2_(w2, p2, acc2);
    }
    float acc = acc2.x + acc2.y;
    #pragma unroll
    for (int off = 16; off; off >>= 1)
        acc += __shfl_xor_sync(0xffffffffu, acc, off);

    if (lane == 0) out[warp] = acc + __ldg(fc_b);
}

// ---------------------------------------------------------------------------
extern "C" void kernel_launch(void* const* d_in, const int* in_sizes, int n_in,
                              void* d_out, int out_size) {
    const float* x    = (const float*)d_in[0];   // (16384, 10)
    const float* ql   = (const float*)d_in[1];   // (6, 10, 3)
    const float* fcw  = (const float*)d_in[2];   // (1, 10)
    const float* fcb  = (const float*)d_in[3];   // (1,)
    float* out = (float*)d_out;                  // (16384, 1)

    precompute_kernel<<<1, 64>>>(ql);
    qcnn_kernel<<<BATCH / 8, 256>>>(x, fcw, fcb, out);
}